// round 1
// baseline (speedup 1.0000x reference)
#include <cuda_runtime.h>
#include <math.h>

#define BB 8
#define CC 512
#define HH 32
#define WW 32
#define LL 1024   // H*W
#define NHD 8
#define HD 64
#define WHALF 16  // WINDOW/2

// ---------------- scratch (static device globals; no runtime allocation) ----
__device__ float g_xwalze[BB*CC*HH*WW];     // (B,C,H,W) post-walze
__device__ float g_comb[BB*LL*2*CC];        // (B*L, 2C): [before | after]
__device__ float g_H[BB*LL*128];            // detector hidden
__device__ float g_mask[BB*LL];             // soft mask
__device__ float g_qkv[BB*LL*3*CC];         // (B*L, 3C)
__device__ float g_ctx[BB*LL*CC];           // attention context (B*L, C)
__device__ float g_attnout[BB*LL*CC];       // out_proj result (B*L, C)

__device__ __forceinline__ float gelu_exact(float v) {
    return 0.5f * v * (1.0f + erff(v * 0.70710678118654752440f));
}

// ---------------- kernel 1: dual depthwise conv + residual + BN + GELU ------
__global__ void walze_kernel(const float* __restrict__ x,
                             const float* __restrict__ dw_w,
                             const float* __restrict__ dw_b,
                             const float* __restrict__ sh_w,
                             const float* __restrict__ sh_b,
                             const float* __restrict__ mixw,
                             const float* __restrict__ gamma,
                             const float* __restrict__ beta)
{
    int idx = blockIdx.x * blockDim.x + threadIdx.x;
    if (idx >= BB*CC*HH*WW) return;
    int w = idx & 31;
    int h = (idx >> 5) & 31;
    int c = (idx >> 10) & 511;
    int b = idx >> 19;

    const float* xb = x + ((size_t)(b*CC + c)) * (HH*WW);
    int hm = (h + HH - 1) & 31, hp = (h + 1) & 31;
    int wm = (w + WW - 1) & 31, wp = (w + 1) & 31;

    float v00 = xb[hm*WW+wm], v01 = xb[hm*WW+w], v02 = xb[hm*WW+wp];
    float v10 = xb[h *WW+wm], v11 = xb[h *WW+w], v12 = xb[h *WW+wp];
    float v20 = xb[hp*WW+wm], v21 = xb[hp*WW+w], v22 = xb[hp*WW+wp];

    const float* dk = dw_w + c*9;
    float main_out = v00*dk[0] + v01*dk[1] + v02*dk[2]
                   + v10*dk[3] + v11*dk[4] + v12*dk[5]
                   + v20*dk[6] + v21*dk[7] + v22*dk[8] + dw_b[c];
    float ex = v00*sh_w[0] + v01*sh_w[1] + v02*sh_w[2]
             + v10*sh_w[3] + v11*sh_w[4] + v12*sh_w[5]
             + v20*sh_w[6] + v21*sh_w[7] + v22*sh_w[8] + sh_b[0];

    float mix = 1.0f / (1.0f + __expf(-mixw[0]));
    float combined = mix * main_out + (1.0f - mix) * ex + v11;
    float bn = gamma[c] * combined * rsqrtf(1.0f + 1e-5f) + beta[c];
    float xw = gelu_exact(bn);

    g_xwalze[idx] = xw;
    int l = h*WW + w;
    size_t base = ((size_t)(b*LL + l)) * (2*CC);
    g_comb[base + c]      = v11;   // x_before
    g_comb[base + CC + c] = xw;    // x_after
}

// ---------------- SGEMM 128x128x8, C = A(M,K) * B(N,K)^T + bias -------------
template<int ACT>
__global__ void __launch_bounds__(256, 2)
sgemm128(const float* __restrict__ A, int lda,
         const float* __restrict__ Bm, int ldb,
         const float* __restrict__ bias,
         float* __restrict__ Cm, int ldc, int K)
{
    __shared__ float As[8][128];
    __shared__ float Bs[8][128];
    int tid = threadIdx.x;
    const int bm = blockIdx.y * 128;
    const int bn = blockIdx.x * 128;
    int arow = tid >> 1;           // 0..127
    int acol = (tid & 1) << 2;     // 0 or 4
    const float* Ap = A + (size_t)(bm + arow) * lda + acol;
    const float* Bp = Bm + (size_t)(bn + arow) * ldb + acol;
    int tx = tid & 15, ty = tid >> 4;

    float acc[8][8];
#pragma unroll
    for (int i = 0; i < 8; i++)
#pragma unroll
        for (int j = 0; j < 8; j++) acc[i][j] = 0.0f;

    for (int k0 = 0; k0 < K; k0 += 8) {
        float4 av = *(const float4*)(Ap + k0);
        float4 bv = *(const float4*)(Bp + k0);
        __syncthreads();
        As[acol+0][arow] = av.x; As[acol+1][arow] = av.y;
        As[acol+2][arow] = av.z; As[acol+3][arow] = av.w;
        Bs[acol+0][arow] = bv.x; Bs[acol+1][arow] = bv.y;
        Bs[acol+2][arow] = bv.z; Bs[acol+3][arow] = bv.w;
        __syncthreads();
#pragma unroll
        for (int k = 0; k < 8; k++) {
            float ar[8], br[8];
#pragma unroll
            for (int i = 0; i < 4; i++) {
                ar[i]   = As[k][ty*4 + i];
                ar[i+4] = As[k][64 + ty*4 + i];
                br[i]   = Bs[k][tx*4 + i];
                br[i+4] = Bs[k][64 + tx*4 + i];
            }
#pragma unroll
            for (int i = 0; i < 8; i++)
#pragma unroll
                for (int j = 0; j < 8; j++)
                    acc[i][j] = fmaf(ar[i], br[j], acc[i][j]);
        }
    }

    float4 bia0 = *(const float4*)(bias + bn + tx*4);
    float4 bia1 = *(const float4*)(bias + bn + 64 + tx*4);
#pragma unroll
    for (int i = 0; i < 8; i++) {
        int row = bm + ((i < 4) ? (ty*4 + i) : (64 + ty*4 + i - 4));
        float o[8];
        o[0] = acc[i][0] + bia0.x; o[1] = acc[i][1] + bia0.y;
        o[2] = acc[i][2] + bia0.z; o[3] = acc[i][3] + bia0.w;
        o[4] = acc[i][4] + bia1.x; o[5] = acc[i][5] + bia1.y;
        o[6] = acc[i][6] + bia1.z; o[7] = acc[i][7] + bia1.w;
        if (ACT == 1) {
#pragma unroll
            for (int j = 0; j < 8; j++) o[j] = gelu_exact(o[j]);
        }
        float* cp0 = Cm + (size_t)row * ldc + bn + tx*4;
        *(float4*)cp0        = make_float4(o[0], o[1], o[2], o[3]);
        *(float4*)(cp0 + 64) = make_float4(o[4], o[5], o[6], o[7]);
    }
}

// ---------------- SGEMM 64x64x16 (for small-N detector GEMM) ----------------
template<int ACT>
__global__ void __launch_bounds__(256)
sgemm64(const float* __restrict__ A, int lda,
        const float* __restrict__ Bm, int ldb,
        const float* __restrict__ bias,
        float* __restrict__ Cm, int ldc, int K)
{
    __shared__ float As[16][64];
    __shared__ float Bs[16][64];
    int tid = threadIdx.x;
    const int bm = blockIdx.y * 64;
    const int bn = blockIdx.x * 64;
    int arow = tid >> 2;           // 0..63
    int acol = (tid & 3) << 2;     // 0,4,8,12
    const float* Ap = A + (size_t)(bm + arow) * lda + acol;
    const float* Bp = Bm + (size_t)(bn + arow) * ldb + acol;
    int tx = tid & 15, ty = tid >> 4;

    float acc[4][4];
#pragma unroll
    for (int i = 0; i < 4; i++)
#pragma unroll
        for (int j = 0; j < 4; j++) acc[i][j] = 0.0f;

    for (int k0 = 0; k0 < K; k0 += 16) {
        float4 av = *(const float4*)(Ap + k0);
        float4 bv = *(const float4*)(Bp + k0);
        __syncthreads();
        As[acol+0][arow] = av.x; As[acol+1][arow] = av.y;
        As[acol+2][arow] = av.z; As[acol+3][arow] = av.w;
        Bs[acol+0][arow] = bv.x; Bs[acol+1][arow] = bv.y;
        Bs[acol+2][arow] = bv.z; Bs[acol+3][arow] = bv.w;
        __syncthreads();
#pragma unroll
        for (int k = 0; k < 16; k++) {
            float ar[4], br[4];
#pragma unroll
            for (int i = 0; i < 4; i++) { ar[i] = As[k][ty*4+i]; br[i] = Bs[k][tx*4+i]; }
#pragma unroll
            for (int i = 0; i < 4; i++)
#pragma unroll
                for (int j = 0; j < 4; j++)
                    acc[i][j] = fmaf(ar[i], br[j], acc[i][j]);
        }
    }

    float4 bia = *(const float4*)(bias + bn + tx*4);
#pragma unroll
    for (int i = 0; i < 4; i++) {
        int row = bm + ty*4 + i;
        float o[4];
        o[0] = acc[i][0] + bia.x; o[1] = acc[i][1] + bia.y;
        o[2] = acc[i][2] + bia.z; o[3] = acc[i][3] + bia.w;
        if (ACT == 1) {
#pragma unroll
            for (int j = 0; j < 4; j++) o[j] = gelu_exact(o[j]);
        }
        *(float4*)(Cm + (size_t)row * ldc + bn + tx*4) = make_float4(o[0],o[1],o[2],o[3]);
    }
}

// ---------------- detector head: logits -> sigmoid mask ---------------------
__global__ void det_final_kernel(const float* __restrict__ w2,
                                 const float* __restrict__ b2)
{
    int gw = (blockIdx.x * blockDim.x + threadIdx.x) >> 5;
    int lane = threadIdx.x & 31;
    if (gw >= BB*LL) return;
    float4 hv = *(const float4*)(g_H + (size_t)gw * 128 + lane*4);
    float4 wv = *(const float4*)(w2 + lane*4);
    float s = hv.x*wv.x + hv.y*wv.y + hv.z*wv.z + hv.w*wv.w;
#pragma unroll
    for (int o = 16; o; o >>= 1) s += __shfl_xor_sync(0xffffffffu, s, o);
    if (lane == 0)
        g_mask[gw] = 1.0f / (1.0f + __expf(-(s + b2[0])));
}

// ---------------- banded attention: one warp per (b, head, query) -----------
__global__ void attn_kernel()
{
    int gw = (blockIdx.x * blockDim.x + threadIdx.x) >> 5;   // 0 .. B*NH*L-1
    int lane = threadIdx.x & 31;
    int q = gw & (LL - 1);
    int h = (gw >> 10) & (NHD - 1);
    int b = gw >> 13;

    const float* qp = g_qkv + (size_t)(b*LL + q) * (3*CC) + h*HD;
    float qa = qp[lane]      * 0.125f;   // 1/sqrt(64)
    float qb = qp[lane + 32] * 0.125f;

    int jlo = max(0, q - WHALF), jhi = min(LL - 1, q + WHALF);
    float m = -1e30f, lsum = 0.0f, acc0 = 0.0f, acc1 = 0.0f;
    for (int j = jlo; j <= jhi; j++) {
        const float* kp = g_qkv + (size_t)(b*LL + j) * (3*CC) + CC + h*HD;
        const float* vp = kp + CC;
        float s = qa * kp[lane] + qb * kp[lane + 32];
#pragma unroll
        for (int o = 16; o; o >>= 1) s += __shfl_xor_sync(0xffffffffu, s, o);
        float mnew = fmaxf(m, s);
        float scale = __expf(m - mnew);
        float p = __expf(s - mnew);
        lsum = lsum * scale + p;
        acc0 = acc0 * scale + p * vp[lane];
        acc1 = acc1 * scale + p * vp[lane + 32];
        m = mnew;
    }
    float inv = 1.0f / lsum;
    float* op = g_ctx + (size_t)(b*LL + q) * CC + h*HD;
    op[lane]      = acc0 * inv;
    op[lane + 32] = acc1 * inv;
}

// ---------------- gated residual combine (output layout B,C,H,W) ------------
__global__ void combine_kernel(float* __restrict__ out)
{
    int idx = blockIdx.x * blockDim.x + threadIdx.x;
    if (idx >= BB*CC*HH*WW) return;
    int l = idx & 1023;
    int c = (idx >> 10) & 511;
    int b = idx >> 19;
    out[idx] = g_xwalze[idx]
             + g_mask[b*LL + l] * g_attnout[(size_t)(b*LL + l) * CC + c];
}

// ---------------- host launcher ---------------------------------------------
extern "C" void kernel_launch(void* const* d_in, const int* in_sizes, int n_in,
                              void* d_out, int out_size)
{
    const float* x      = (const float*)d_in[0];
    const float* dw_w   = (const float*)d_in[1];
    const float* dw_b   = (const float*)d_in[2];
    const float* sh_w   = (const float*)d_in[3];
    const float* sh_b   = (const float*)d_in[4];
    const float* mixw   = (const float*)d_in[5];
    const float* gamma  = (const float*)d_in[6];
    const float* beta   = (const float*)d_in[7];
    const float* det_w1 = (const float*)d_in[8];
    const float* det_b1 = (const float*)d_in[9];
    const float* det_w2 = (const float*)d_in[10];
    const float* det_b2 = (const float*)d_in[11];
    const float* ipw    = (const float*)d_in[12];
    const float* ipb    = (const float*)d_in[13];
    const float* opw    = (const float*)d_in[14];
    const float* opb    = (const float*)d_in[15];
    float* out = (float*)d_out;

    float *p_comb, *p_H, *p_qkv, *p_ctx, *p_attnout;
    cudaGetSymbolAddress((void**)&p_comb,    g_comb);
    cudaGetSymbolAddress((void**)&p_H,       g_H);
    cudaGetSymbolAddress((void**)&p_qkv,     g_qkv);
    cudaGetSymbolAddress((void**)&p_ctx,     g_ctx);
    cudaGetSymbolAddress((void**)&p_attnout, g_attnout);

    const int NTOT = BB*CC*HH*WW;   // 4,194,304
    const int M = BB*LL;            // 8192

    // 1) walze: dwconv + BN + GELU, produce spatial + comb layouts
    walze_kernel<<<NTOT/256, 256>>>(x, dw_w, dw_b, sh_w, sh_b, mixw, gamma, beta);

    // 2) detector GEMM: H = gelu(comb(8192,1024) @ det_w1^T(1024,128) + b1)
    {
        dim3 g(128/64, M/64);
        sgemm64<1><<<g, 256>>>(p_comb, 2*CC, det_w1, 2*CC, det_b1, p_H, 128, 2*CC);
    }
    // 3) detector head -> mask
    det_final_kernel<<<(M*32)/256, 256>>>(det_w2, det_b2);

    // 4) QKV GEMM: qkv = x_after(8192,512) @ in_proj_w^T(512,1536) + b
    {
        dim3 g((3*CC)/128, M/128);
        sgemm128<0><<<g, 256>>>(p_comb + CC, 2*CC, ipw, CC, ipb, p_qkv, 3*CC, CC);
    }

    // 5) banded attention
    attn_kernel<<<(BB*NHD*LL*32)/256, 256>>>();

    // 6) out_proj GEMM
    {
        dim3 g(CC/128, M/128);
        sgemm128<0><<<g, 256>>>(p_ctx, CC, opw, CC, opb, p_attnout, CC, CC);
    }

    // 7) gated residual combine
    combine_kernel<<<NTOT/256, 256>>>(out);
}

// round 3
// speedup vs baseline: 2.2381x; 2.2381x over previous
#include <cuda_runtime.h>
#include <math.h>
#include <stdint.h>

#define BB 8
#define CC 512
#define HH 32
#define WW 32
#define LL 1024   // H*W
#define NHD 8
#define HD 64
#define WHALF 16  // WINDOW/2

// ---------------- scratch (static device globals; no runtime allocation) ----
__device__ float g_xwalze[BB*CC*HH*WW];     // (B,C,H,W) post-walze
__device__ float g_comb[BB*LL*2*CC];        // (B*L, 2C): [before | after], tf32-rounded
__device__ float g_H[BB*LL*128];            // detector hidden
__device__ float g_mask[BB*LL];             // soft mask
__device__ float g_qkv[BB*LL*3*CC];         // (B*L, 3C)
__device__ float g_ctx[BB*LL*CC];           // attention context, tf32-rounded
__device__ float g_attnout[BB*LL*CC];       // out_proj result (B*L, C)
__device__ float g_ipw[3*CC*CC];            // tf32-rounded in_proj_w
__device__ float g_opw[CC*CC];              // tf32-rounded out_proj_w
__device__ float g_w1[128*2*CC];            // tf32-rounded det_w1

__device__ __forceinline__ float gelu_exact(float v) {
    return 0.5f * v * (1.0f + erff(v * 0.70710678118654752440f));
}
__device__ __forceinline__ float to_tf32(float x) {
    uint32_t r;
    asm("cvt.rna.tf32.f32 %0, %1;" : "=r"(r) : "f"(x));
    return __uint_as_float(r);
}
__device__ __forceinline__ uint32_t smem_u32(const void* p) {
    uint32_t a;
    asm("{ .reg .u64 t; cvta.to.shared.u64 t, %1; cvt.u32.u64 %0, t; }"
        : "=r"(a) : "l"(p));
    return a;
}
__device__ __forceinline__ void cp16(uint32_t dst, const void* src) {
    asm volatile("cp.async.cg.shared.global [%0], [%1], 16;" :: "r"(dst), "l"(src));
}
__device__ __forceinline__ void ldmx4(uint32_t addr, uint32_t& r0, uint32_t& r1,
                                      uint32_t& r2, uint32_t& r3) {
    asm volatile("ldmatrix.sync.aligned.m8n8.x4.shared.b16 {%0,%1,%2,%3}, [%4];"
                 : "=r"(r0), "=r"(r1), "=r"(r2), "=r"(r3) : "r"(addr));
}
__device__ __forceinline__ void mma8(float* c, uint32_t a0, uint32_t a1,
                                     uint32_t a2, uint32_t a3,
                                     uint32_t b0, uint32_t b1) {
    asm volatile("mma.sync.aligned.m16n8k8.row.col.f32.tf32.tf32.f32 "
                 "{%0,%1,%2,%3}, {%4,%5,%6,%7}, {%8,%9}, {%0,%1,%2,%3};"
                 : "+f"(c[0]), "+f"(c[1]), "+f"(c[2]), "+f"(c[3])
                 : "r"(a0), "r"(a1), "r"(a2), "r"(a3), "r"(b0), "r"(b1));
}

// ====== tf32 mma.sync GEMM: C(M,N) = A(M,K) * B(N,K)^T + bias ===============
// CTA tile 128x128, 256 threads = 8 warps (2 m x 4 n), warp tile 64x32.
// K-step 32 floats (128B rows), double-buffered cp.async, xor-swizzled smem.
// A, B inputs MUST already be tf32-rounded (mma truncation is then exact).
#define GEMM_SMEM (4 * 16384)   // A0,B0,A1,B1

template<int ACT>
__global__ void __launch_bounds__(256, 2)
mma_gemm(const float* __restrict__ A, int lda,
         const float* __restrict__ Bm, int ldb,
         const float* __restrict__ bias,
         float* __restrict__ Cm, int ldc, int K)
{
    extern __shared__ char smem[];
    const uint32_t sb = smem_u32(smem);
    const int tid = threadIdx.x, lane = tid & 31, wid = tid >> 5;
    const int bm = blockIdx.y * 128, bn = blockIdx.x * 128;
    const int wm0 = (wid & 1) * 64, wn0 = (wid >> 1) * 32;

    // cp.async mapping: 8 threads per 128B row, 32 rows per pass, 4 passes
    const int ld_row = tid >> 3;
    const int ld_kb  = (tid & 7) * 16;                  // byte off in row
    const uint32_t st_off = (uint32_t)(ld_row * 128 + (ld_kb ^ ((ld_row & 7) << 4)));
    const float* Agb = A  + (size_t)(bm + ld_row) * lda + (tid & 7) * 4;
    const float* Bgb = Bm + (size_t)(bn + ld_row) * ldb + (tid & 7) * 4;

    auto load_tile = [&](int buf, int ch) {
        uint32_t da = sb + buf * 32768 + st_off;
        uint32_t db = da + 16384;
        const float* sa = Agb + ch * 32;
        const float* sbp = Bgb + ch * 32;
#pragma unroll
        for (int p = 0; p < 4; p++) {
            cp16(da + p * 4096, sa + (size_t)p * 32 * lda);
            cp16(db + p * 4096, sbp + (size_t)p * 32 * ldb);
        }
        asm volatile("cp.async.commit_group;" ::: "memory");
    };

    // fragment lane addressing (swizzle xor-term constant per lane)
    const int arow  = wm0 + (lane & 15);
    const uint32_t akb = ((uint32_t)(lane >> 4)) << 4;       // 0 or 16B
    const uint32_t aswz = (uint32_t)((arow & 7) << 4);
    const uint32_t a_rowbase = (uint32_t)(arow * 128);
    const int brow  = wn0 + ((lane >> 4) << 3) + (lane & 7);
    const uint32_t bkb = (uint32_t)(((lane >> 3) & 1) << 4);
    const uint32_t bswz = (uint32_t)((brow & 7) << 4);
    const uint32_t b_rowbase = (uint32_t)(16384 + brow * 128);

    float c[4][4][4];
#pragma unroll
    for (int i = 0; i < 4; i++)
#pragma unroll
        for (int j = 0; j < 4; j++)
#pragma unroll
            for (int k = 0; k < 4; k++) c[i][j][k] = 0.0f;

    const int nch = K >> 5;
    load_tile(0, 0);
    load_tile(1, 1);

    for (int ch = 0; ch < nch; ch++) {
        const int buf = ch & 1;
        if (ch + 1 < nch) asm volatile("cp.async.wait_group 1;" ::: "memory");
        else              asm volatile("cp.async.wait_group 0;" ::: "memory");
        __syncthreads();

        const uint32_t base = sb + buf * 32768;
#pragma unroll
        for (int ks = 0; ks < 4; ks++) {
            const uint32_t kso = (uint32_t)(ks * 32);
            uint32_t a[4][4];
#pragma unroll
            for (int mt = 0; mt < 4; mt++)
                ldmx4(base + a_rowbase + (uint32_t)(mt * 2048) + ((kso + akb) ^ aswz),
                      a[mt][0], a[mt][1], a[mt][2], a[mt][3]);
            uint32_t b[4][2];
#pragma unroll
            for (int nt2 = 0; nt2 < 2; nt2++)
                ldmx4(base + b_rowbase + (uint32_t)(nt2 * 2048) + ((kso + bkb) ^ bswz),
                      b[nt2*2][0], b[nt2*2][1], b[nt2*2+1][0], b[nt2*2+1][1]);
#pragma unroll
            for (int mt = 0; mt < 4; mt++)
#pragma unroll
                for (int nt = 0; nt < 4; nt++)
                    mma8(c[mt][nt], a[mt][0], a[mt][1], a[mt][2], a[mt][3],
                         b[nt][0], b[nt][1]);
        }
        __syncthreads();
        if (ch + 2 < nch) load_tile(buf, ch + 2);
    }

    // epilogue: direct st.v2 per fragment
#pragma unroll
    for (int mt = 0; mt < 4; mt++) {
        const int r0 = bm + wm0 + mt * 16 + (lane >> 2);
#pragma unroll
        for (int nt = 0; nt < 4; nt++) {
            const int col = bn + wn0 + nt * 8 + (lane & 3) * 2;
            float2 bs = *(const float2*)(bias + col);
            float v0 = c[mt][nt][0] + bs.x, v1 = c[mt][nt][1] + bs.y;
            float v2 = c[mt][nt][2] + bs.x, v3 = c[mt][nt][3] + bs.y;
            if (ACT) {
                v0 = gelu_exact(v0); v1 = gelu_exact(v1);
                v2 = gelu_exact(v2); v3 = gelu_exact(v3);
            }
            *(float2*)(Cm + (size_t)r0 * ldc + col)       = make_float2(v0, v1);
            *(float2*)(Cm + (size_t)(r0 + 8) * ldc + col) = make_float2(v2, v3);
        }
    }
}

// ---------------- weight rounding to tf32 (once per launch) -----------------
__global__ void round_weights(const float* __restrict__ ipw,
                              const float* __restrict__ opw,
                              const float* __restrict__ w1)
{
    int i = blockIdx.x * blockDim.x + threadIdx.x;
    const int N1 = 3*CC*CC, N2 = CC*CC, N3 = 128*2*CC;
    if (i < N1)            g_ipw[i] = to_tf32(ipw[i]);
    else if (i < N1 + N2)  g_opw[i - N1] = to_tf32(opw[i - N1]);
    else if (i < N1 + N2 + N3) g_w1[i - N1 - N2] = to_tf32(w1[i - N1 - N2]);
}

// ---------------- kernel 1: dual depthwise conv + residual + BN + GELU ------
__global__ void walze_kernel(const float* __restrict__ x,
                             const float* __restrict__ dw_w,
                             const float* __restrict__ dw_b,
                             const float* __restrict__ sh_w,
                             const float* __restrict__ sh_b,
                             const float* __restrict__ mixw,
                             const float* __restrict__ gamma,
                             const float* __restrict__ beta)
{
    int idx = blockIdx.x * blockDim.x + threadIdx.x;
    if (idx >= BB*CC*HH*WW) return;
    int w = idx & 31;
    int h = (idx >> 5) & 31;
    int c = (idx >> 10) & 511;
    int b = idx >> 19;

    const float* xb = x + ((size_t)(b*CC + c)) * (HH*WW);
    int hm = (h + HH - 1) & 31, hp = (h + 1) & 31;
    int wm = (w + WW - 1) & 31, wp = (w + 1) & 31;

    float v00 = xb[hm*WW+wm], v01 = xb[hm*WW+w], v02 = xb[hm*WW+wp];
    float v10 = xb[h *WW+wm], v11 = xb[h *WW+w], v12 = xb[h *WW+wp];
    float v20 = xb[hp*WW+wm], v21 = xb[hp*WW+w], v22 = xb[hp*WW+wp];

    const float* dk = dw_w + c*9;
    float main_out = v00*dk[0] + v01*dk[1] + v02*dk[2]
                   + v10*dk[3] + v11*dk[4] + v12*dk[5]
                   + v20*dk[6] + v21*dk[7] + v22*dk[8] + dw_b[c];
    float ex = v00*sh_w[0] + v01*sh_w[1] + v02*sh_w[2]
             + v10*sh_w[3] + v11*sh_w[4] + v12*sh_w[5]
             + v20*sh_w[6] + v21*sh_w[7] + v22*sh_w[8] + sh_b[0];

    float mix = 1.0f / (1.0f + __expf(-mixw[0]));
    float combined = mix * main_out + (1.0f - mix) * ex + v11;
    float bn = gamma[c] * combined * rsqrtf(1.0f + 1e-5f) + beta[c];
    float xw = gelu_exact(bn);

    g_xwalze[idx] = xw;
    int l = h*WW + w;
    size_t base = ((size_t)(b*LL + l)) * (2*CC);
    g_comb[base + c]      = to_tf32(v11);   // x_before (tf32 for GEMM A)
    g_comb[base + CC + c] = to_tf32(xw);    // x_after  (tf32 for GEMM A)
}

// ---------------- detector head: logits -> sigmoid mask ---------------------
__global__ void det_final_kernel(const float* __restrict__ w2,
                                 const float* __restrict__ b2)
{
    int gw = (blockIdx.x * blockDim.x + threadIdx.x) >> 5;
    int lane = threadIdx.x & 31;
    if (gw >= BB*LL) return;
    float4 hv = *(const float4*)(g_H + (size_t)gw * 128 + lane*4);
    float4 wv = *(const float4*)(w2 + lane*4);
    float s = hv.x*wv.x + hv.y*wv.y + hv.z*wv.z + hv.w*wv.w;
#pragma unroll
    for (int o = 16; o; o >>= 1) s += __shfl_xor_sync(0xffffffffu, s, o);
    if (lane == 0)
        g_mask[gw] = 1.0f / (1.0f + __expf(-(s + b2[0])));
}

// ---------------- banded attention: one warp per (b, head, query) -----------
__global__ void attn_kernel()
{
    int gw = (blockIdx.x * blockDim.x + threadIdx.x) >> 5;   // 0 .. B*NH*L-1
    int lane = threadIdx.x & 31;
    int q = gw & (LL - 1);
    int h = (gw >> 10) & (NHD - 1);
    int b = gw >> 13;

    const float* qp = g_qkv + (size_t)(b*LL + q) * (3*CC) + h*HD;
    float qa = qp[lane]      * 0.125f;   // 1/sqrt(64)
    float qb = qp[lane + 32] * 0.125f;

    int jlo = max(0, q - WHALF), jhi = min(LL - 1, q + WHALF);
    float m = -1e30f, lsum = 0.0f, acc0 = 0.0f, acc1 = 0.0f;
    for (int j = jlo; j <= jhi; j++) {
        const float* kp = g_qkv + (size_t)(b*LL + j) * (3*CC) + CC + h*HD;
        const float* vp = kp + CC;
        float s = qa * kp[lane] + qb * kp[lane + 32];
#pragma unroll
        for (int o = 16; o; o >>= 1) s += __shfl_xor_sync(0xffffffffu, s, o);
        float mnew = fmaxf(m, s);
        float scale = __expf(m - mnew);
        float p = __expf(s - mnew);
        lsum = lsum * scale + p;
        acc0 = acc0 * scale + p * vp[lane];
        acc1 = acc1 * scale + p * vp[lane + 32];
        m = mnew;
    }
    float inv = 1.0f / lsum;
    float* op = g_ctx + (size_t)(b*LL + q) * CC + h*HD;
    op[lane]      = to_tf32(acc0 * inv);   // tf32 for out_proj GEMM A
    op[lane + 32] = to_tf32(acc1 * inv);
}

// ---------------- gated residual combine (output layout B,C,H,W) ------------
__global__ void combine_kernel(float* __restrict__ out)
{
    int idx = blockIdx.x * blockDim.x + threadIdx.x;
    if (idx >= BB*CC*HH*WW) return;
    int l = idx & 1023;
    int c = (idx >> 10) & 511;
    int b = idx >> 19;
    out[idx] = g_xwalze[idx]
             + g_mask[b*LL + l] * g_attnout[(size_t)(b*LL + l) * CC + c];
}

// ---------------- host launcher ---------------------------------------------
extern "C" void kernel_launch(void* const* d_in, const int* in_sizes, int n_in,
                              void* d_out, int out_size)
{
    const float* x      = (const float*)d_in[0];
    const float* dw_w   = (const float*)d_in[1];
    const float* dw_b   = (const float*)d_in[2];
    const float* sh_w   = (const float*)d_in[3];
    const float* sh_b   = (const float*)d_in[4];
    const float* mixw   = (const float*)d_in[5];
    const float* gamma  = (const float*)d_in[6];
    const float* beta   = (const float*)d_in[7];
    const float* det_w1 = (const float*)d_in[8];
    const float* det_b1 = (const float*)d_in[9];
    const float* det_w2 = (const float*)d_in[10];
    const float* det_b2 = (const float*)d_in[11];
    const float* ipw    = (const float*)d_in[12];
    const float* ipb    = (const float*)d_in[13];
    const float* opw    = (const float*)d_in[14];
    const float* opb    = (const float*)d_in[15];
    float* out = (float*)d_out;

    float *p_comb, *p_H, *p_qkv, *p_ctx, *p_attnout, *p_ipw, *p_opw, *p_w1;
    cudaGetSymbolAddress((void**)&p_comb,    g_comb);
    cudaGetSymbolAddress((void**)&p_H,       g_H);
    cudaGetSymbolAddress((void**)&p_qkv,     g_qkv);
    cudaGetSymbolAddress((void**)&p_ctx,     g_ctx);
    cudaGetSymbolAddress((void**)&p_attnout, g_attnout);
    cudaGetSymbolAddress((void**)&p_ipw,     g_ipw);
    cudaGetSymbolAddress((void**)&p_opw,     g_opw);
    cudaGetSymbolAddress((void**)&p_w1,      g_w1);

    cudaFuncSetAttribute(mma_gemm<0>, cudaFuncAttributeMaxDynamicSharedMemorySize,
                         GEMM_SMEM);
    cudaFuncSetAttribute(mma_gemm<1>, cudaFuncAttributeMaxDynamicSharedMemorySize,
                         GEMM_SMEM);

    const int NTOT = BB*CC*HH*WW;   // 4,194,304
    const int M = BB*LL;            // 8192

    // 0) round weights to tf32 once
    {
        int tot = 3*CC*CC + CC*CC + 128*2*CC;
        round_weights<<<(tot + 255)/256, 256>>>(ipw, opw, det_w1);
    }

    // 1) walze: dwconv + BN + GELU, produce spatial + comb layouts
    walze_kernel<<<NTOT/256, 256>>>(x, dw_w, dw_b, sh_w, sh_b, mixw, gamma, beta);

    // 2) detector GEMM: H = gelu(comb(8192,1024) @ det_w1^T + b1), N=128, K=1024
    {
        dim3 g(1, M/128);
        mma_gemm<1><<<g, 256, GEMM_SMEM>>>(p_comb, 2*CC, p_w1, 2*CC,
                                           det_b1, p_H, 128, 2*CC);
    }
    // 3) detector head -> mask
    det_final_kernel<<<(M*32)/256, 256>>>(det_w2, det_b2);

    // 4) QKV GEMM: qkv = x_after(8192,512) @ in_proj_w^T(512,1536) + b
    {
        dim3 g((3*CC)/128, M/128);
        mma_gemm<0><<<g, 256, GEMM_SMEM>>>(p_comb + CC, 2*CC, p_ipw, CC,
                                           ipb, p_qkv, 3*CC, CC);
    }

    // 5) banded attention
    attn_kernel<<<(BB*NHD*LL*32)/256, 256>>>();

    // 6) out_proj GEMM: N=512, K=512
    {
        dim3 g(CC/128, M/128);
        mma_gemm<0><<<g, 256, GEMM_SMEM>>>(p_ctx, CC, p_opw, CC,
                                           opb, p_attnout, CC, CC);
    }

    // 7) gated residual combine
    combine_kernel<<<NTOT/256, 256>>>(out);
}

// round 4
// speedup vs baseline: 2.8996x; 1.2955x over previous
#include <cuda_runtime.h>
#include <math.h>
#include <stdint.h>

#define BB 8
#define CC 512
#define HH 32
#define WW 32
#define LL 1024   // H*W
#define NHD 8
#define HD 64
#define WHALF 16  // WINDOW/2

// ---------------- scratch (static device globals; no runtime allocation) ----
__device__ float g_xwalze[BB*CC*HH*WW];     // (B,C,H,W) post-walze
__device__ float g_comb[BB*LL*2*CC];        // (B*L, 2C): [before | after], tf32-rounded
__device__ float g_H[BB*LL*128];            // detector hidden
__device__ float g_mask[BB*LL];             // soft mask
__device__ float g_qkv[BB*LL*3*CC];         // (B*L, 3C)
__device__ float g_ctx[BB*LL*CC];           // attention context, tf32-rounded
__device__ float g_attnout[BB*LL*CC];       // out_proj result (B*L, C)
__device__ float g_ipw[3*CC*CC];            // tf32-rounded in_proj_w
__device__ float g_opw[CC*CC];              // tf32-rounded out_proj_w
__device__ float g_w1[128*2*CC];            // tf32-rounded det_w1

__device__ __forceinline__ float gelu_exact(float v) {
    return 0.5f * v * (1.0f + erff(v * 0.70710678118654752440f));
}
__device__ __forceinline__ float to_tf32(float x) {
    uint32_t r;
    asm("cvt.rna.tf32.f32 %0, %1;" : "=r"(r) : "f"(x));
    return __uint_as_float(r);
}
__device__ __forceinline__ uint32_t smem_u32(const void* p) {
    uint32_t a;
    asm("{ .reg .u64 t; cvta.to.shared.u64 t, %1; cvt.u32.u64 %0, t; }"
        : "=r"(a) : "l"(p));
    return a;
}
__device__ __forceinline__ void cp16(uint32_t dst, const void* src) {
    asm volatile("cp.async.cg.shared.global [%0], [%1], 16;" :: "r"(dst), "l"(src));
}
__device__ __forceinline__ void ldmx4(uint32_t addr, uint32_t& r0, uint32_t& r1,
                                      uint32_t& r2, uint32_t& r3) {
    asm volatile("ldmatrix.sync.aligned.m8n8.x4.shared.b16 {%0,%1,%2,%3}, [%4];"
                 : "=r"(r0), "=r"(r1), "=r"(r2), "=r"(r3) : "r"(addr));
}
__device__ __forceinline__ void mma8(float* c, uint32_t a0, uint32_t a1,
                                     uint32_t a2, uint32_t a3,
                                     uint32_t b0, uint32_t b1) {
    asm volatile("mma.sync.aligned.m16n8k8.row.col.f32.tf32.tf32.f32 "
                 "{%0,%1,%2,%3}, {%4,%5,%6,%7}, {%8,%9}, {%0,%1,%2,%3};"
                 : "+f"(c[0]), "+f"(c[1]), "+f"(c[2]), "+f"(c[3])
                 : "r"(a0), "r"(a1), "r"(a2), "r"(a3), "r"(b0), "r"(b1));
}

// ====== tf32 mma.sync GEMM: C(M,N) = A(M,K) * B(N,K)^T + bias (validated) ===
#define GEMM_SMEM (4 * 16384)   // A0,B0,A1,B1

template<int ACT>
__global__ void __launch_bounds__(256, 2)
mma_gemm(const float* __restrict__ A, int lda,
         const float* __restrict__ Bm, int ldb,
         const float* __restrict__ bias,
         float* __restrict__ Cm, int ldc, int K)
{
    extern __shared__ char smem[];
    const uint32_t sb = smem_u32(smem);
    const int tid = threadIdx.x, lane = tid & 31, wid = tid >> 5;
    const int bm = blockIdx.y * 128, bn = blockIdx.x * 128;
    const int wm0 = (wid & 1) * 64, wn0 = (wid >> 1) * 32;

    const int ld_row = tid >> 3;
    const int ld_kb  = (tid & 7) * 16;
    const uint32_t st_off = (uint32_t)(ld_row * 128 + (ld_kb ^ ((ld_row & 7) << 4)));
    const float* Agb = A  + (size_t)(bm + ld_row) * lda + (tid & 7) * 4;
    const float* Bgb = Bm + (size_t)(bn + ld_row) * ldb + (tid & 7) * 4;

    auto load_tile = [&](int buf, int ch) {
        uint32_t da = sb + buf * 32768 + st_off;
        uint32_t db = da + 16384;
        const float* sa = Agb + ch * 32;
        const float* sbp = Bgb + ch * 32;
#pragma unroll
        for (int p = 0; p < 4; p++) {
            cp16(da + p * 4096, sa + (size_t)p * 32 * lda);
            cp16(db + p * 4096, sbp + (size_t)p * 32 * ldb);
        }
        asm volatile("cp.async.commit_group;" ::: "memory");
    };

    const int arow  = wm0 + (lane & 15);
    const uint32_t akb = ((uint32_t)(lane >> 4)) << 4;
    const uint32_t aswz = (uint32_t)((arow & 7) << 4);
    const uint32_t a_rowbase = (uint32_t)(arow * 128);
    const int brow  = wn0 + ((lane >> 4) << 3) + (lane & 7);
    const uint32_t bkb = (uint32_t)(((lane >> 3) & 1) << 4);
    const uint32_t bswz = (uint32_t)((brow & 7) << 4);
    const uint32_t b_rowbase = (uint32_t)(16384 + brow * 128);

    float c[4][4][4];
#pragma unroll
    for (int i = 0; i < 4; i++)
#pragma unroll
        for (int j = 0; j < 4; j++)
#pragma unroll
            for (int k = 0; k < 4; k++) c[i][j][k] = 0.0f;

    const int nch = K >> 5;
    load_tile(0, 0);
    load_tile(1, 1);

    for (int ch = 0; ch < nch; ch++) {
        const int buf = ch & 1;
        if (ch + 1 < nch) asm volatile("cp.async.wait_group 1;" ::: "memory");
        else              asm volatile("cp.async.wait_group 0;" ::: "memory");
        __syncthreads();

        const uint32_t base = sb + buf * 32768;
#pragma unroll
        for (int ks = 0; ks < 4; ks++) {
            const uint32_t kso = (uint32_t)(ks * 32);
            uint32_t a[4][4];
#pragma unroll
            for (int mt = 0; mt < 4; mt++)
                ldmx4(base + a_rowbase + (uint32_t)(mt * 2048) + ((kso + akb) ^ aswz),
                      a[mt][0], a[mt][1], a[mt][2], a[mt][3]);
            uint32_t b[4][2];
#pragma unroll
            for (int nt2 = 0; nt2 < 2; nt2++)
                ldmx4(base + b_rowbase + (uint32_t)(nt2 * 2048) + ((kso + bkb) ^ bswz),
                      b[nt2*2][0], b[nt2*2][1], b[nt2*2+1][0], b[nt2*2+1][1]);
#pragma unroll
            for (int mt = 0; mt < 4; mt++)
#pragma unroll
                for (int nt = 0; nt < 4; nt++)
                    mma8(c[mt][nt], a[mt][0], a[mt][1], a[mt][2], a[mt][3],
                         b[nt][0], b[nt][1]);
        }
        __syncthreads();
        if (ch + 2 < nch) load_tile(buf, ch + 2);
    }

#pragma unroll
    for (int mt = 0; mt < 4; mt++) {
        const int r0 = bm + wm0 + mt * 16 + (lane >> 2);
#pragma unroll
        for (int nt = 0; nt < 4; nt++) {
            const int col = bn + wn0 + nt * 8 + (lane & 3) * 2;
            float2 bs = *(const float2*)(bias + col);
            float v0 = c[mt][nt][0] + bs.x, v1 = c[mt][nt][1] + bs.y;
            float v2 = c[mt][nt][2] + bs.x, v3 = c[mt][nt][3] + bs.y;
            if (ACT) {
                v0 = gelu_exact(v0); v1 = gelu_exact(v1);
                v2 = gelu_exact(v2); v3 = gelu_exact(v3);
            }
            *(float2*)(Cm + (size_t)r0 * ldc + col)       = make_float2(v0, v1);
            *(float2*)(Cm + (size_t)(r0 + 8) * ldc + col) = make_float2(v2, v3);
        }
    }
}

// ---------------- weight rounding to tf32 (once per launch) -----------------
__global__ void round_weights(const float* __restrict__ ipw,
                              const float* __restrict__ opw,
                              const float* __restrict__ w1)
{
    int i = blockIdx.x * blockDim.x + threadIdx.x;
    const int N1 = 3*CC*CC, N2 = CC*CC, N3 = 128*2*CC;
    if (i < N1)            g_ipw[i] = to_tf32(ipw[i]);
    else if (i < N1 + N2)  g_opw[i - N1] = to_tf32(opw[i - N1]);
    else if (i < N1 + N2 + N3) g_w1[i - N1 - N2] = to_tf32(w1[i - N1 - N2]);
}

// ---------------- kernel 1: dual depthwise conv + residual + BN + GELU ------
// Writes ONLY g_xwalze (coalesced, same layout as x). comb built by pack_kernel.
__global__ void walze_kernel(const float* __restrict__ x,
                             const float* __restrict__ dw_w,
                             const float* __restrict__ dw_b,
                             const float* __restrict__ sh_w,
                             const float* __restrict__ sh_b,
                             const float* __restrict__ mixw,
                             const float* __restrict__ gamma,
                             const float* __restrict__ beta)
{
    int idx = blockIdx.x * blockDim.x + threadIdx.x;
    if (idx >= BB*CC*HH*WW) return;
    int w = idx & 31;
    int h = (idx >> 5) & 31;
    int c = (idx >> 10) & 511;
    int b = idx >> 19;

    const float* xb = x + ((size_t)(b*CC + c)) * (HH*WW);
    int hm = (h + HH - 1) & 31, hp = (h + 1) & 31;
    int wm = (w + WW - 1) & 31, wp = (w + 1) & 31;

    float v00 = xb[hm*WW+wm], v01 = xb[hm*WW+w], v02 = xb[hm*WW+wp];
    float v10 = xb[h *WW+wm], v11 = xb[h *WW+w], v12 = xb[h *WW+wp];
    float v20 = xb[hp*WW+wm], v21 = xb[hp*WW+w], v22 = xb[hp*WW+wp];

    const float* dk = dw_w + c*9;
    float main_out = v00*dk[0] + v01*dk[1] + v02*dk[2]
                   + v10*dk[3] + v11*dk[4] + v12*dk[5]
                   + v20*dk[6] + v21*dk[7] + v22*dk[8] + dw_b[c];
    float ex = v00*sh_w[0] + v01*sh_w[1] + v02*sh_w[2]
             + v10*sh_w[3] + v11*sh_w[4] + v12*sh_w[5]
             + v20*sh_w[6] + v21*sh_w[7] + v22*sh_w[8] + sh_b[0];

    float mix = 1.0f / (1.0f + __expf(-mixw[0]));
    float combined = mix * main_out + (1.0f - mix) * ex + v11;
    float bn = gamma[c] * combined * rsqrtf(1.0f + 1e-5f) + beta[c];
    g_xwalze[idx] = gelu_exact(bn);
}

// ---------------- pack: transpose x / x_walze into comb rows (tf32) ---------
// grid: b(8) x ct(16) x lt(32) tiles of 32c x 32l; all streams coalesced.
__global__ void __launch_bounds__(256)
pack_kernel(const float* __restrict__ x)
{
    __shared__ float sx[32][33];
    __shared__ float sw[32][33];
    int bi = blockIdx.x;
    int lt = bi & 31, ct = (bi >> 5) & 15, b = bi >> 9;
    int c0 = ct * 32, l0 = lt * 32;
    int tx = threadIdx.x & 31, ty = threadIdx.x >> 5;
#pragma unroll
    for (int r = ty; r < 32; r += 8) {
        size_t src = (size_t)(b*CC + c0 + r) * LL + l0 + tx;
        sx[r][tx] = x[src];
        sw[r][tx] = g_xwalze[src];
    }
    __syncthreads();
#pragma unroll
    for (int r = ty; r < 32; r += 8) {   // r = local l index
        size_t dst = (size_t)(b*LL + l0 + r) * (2*CC) + c0 + tx;
        g_comb[dst]      = to_tf32(sx[tx][r]);
        g_comb[dst + CC] = to_tf32(sw[tx][r]);
    }
}

// ---------------- detector head: logits -> sigmoid mask ---------------------
__global__ void det_final_kernel(const float* __restrict__ w2,
                                 const float* __restrict__ b2)
{
    int gw = (blockIdx.x * blockDim.x + threadIdx.x) >> 5;
    int lane = threadIdx.x & 31;
    if (gw >= BB*LL) return;
    float4 hv = *(const float4*)(g_H + (size_t)gw * 128 + lane*4);
    float4 wv = *(const float4*)(w2 + lane*4);
    float s = hv.x*wv.x + hv.y*wv.y + hv.z*wv.z + hv.w*wv.w;
#pragma unroll
    for (int o = 16; o; o >>= 1) s += __shfl_xor_sync(0xffffffffu, s, o);
    if (lane == 0)
        g_mask[gw] = 1.0f / (1.0f + __expf(-(s + b2[0])));
}

// ---------------- banded attention: smem-tiled, 2 queries per warp ----------
// Block = (b, head, 64-query tile). K/V band (<=96 rows x 64) staged in smem.
// Lanes 0-15 -> query A, 16-31 -> query B; each lane owns 4 dims (float4).
__global__ void __launch_bounds__(256)
attn_kernel()
{
    __shared__ float ks[96*64];
    __shared__ float vs[96*64];
    int bi = blockIdx.x;                   // 0..1023
    int qt = bi & 15;
    int h  = (bi >> 4) & 7;
    int b  = bi >> 7;
    int q0 = qt * 64;
    int jlo = max(0, q0 - WHALF);
    int jhi = min(LL - 1, q0 + 63 + WHALF);
    int nrows = jhi - jlo + 1;             // <= 96
    int tid = threadIdx.x;

    const float* kbase = g_qkv + (size_t)(b*LL + jlo) * (3*CC) + CC + h*HD;
    for (int i = tid; i < nrows * 16; i += 256) {
        int r = i >> 4, c = (i & 15) * 4;
        const float* kp = kbase + (size_t)r * (3*CC) + c;
        *(float4*)(ks + r*64 + c) = *(const float4*)kp;
        *(float4*)(vs + r*64 + c) = *(const float4*)(kp + CC);
    }
    __syncthreads();

    int wid = tid >> 5, lane = tid & 31;
    int half = lane >> 4;                  // which query of the pair
    int dl = lane & 15;                    // dims 4*dl .. 4*dl+3

#pragma unroll
    for (int pass = 0; pass < 4; pass++) {
        int qe = q0 + wid*8 + pass*2;      // even query of the pair
        int q  = qe + half;
        const float* qp = g_qkv + (size_t)(b*LL + q) * (3*CC) + h*HD + dl*4;
        float4 qv = *(const float4*)qp;
        qv.x *= 0.125f; qv.y *= 0.125f; qv.z *= 0.125f; qv.w *= 0.125f;

        int wlo = max(0, q - WHALF), whi = min(LL - 1, q + WHALF);
        int plo = max(0, qe - WHALF) - jlo;
        int phi = min(LL - 1, qe + 1 + WHALF) - jlo;

        float lsum = 0.0f;
        float4 acc = make_float4(0.f, 0.f, 0.f, 0.f);
        for (int j = plo; j <= phi; j++) {
            float4 kv = *(const float4*)(ks + j*64 + dl*4);
            float s = qv.x*kv.x + qv.y*kv.y + qv.z*kv.z + qv.w*kv.w;
            s += __shfl_xor_sync(0xffffffffu, s, 8);
            s += __shfl_xor_sync(0xffffffffu, s, 4);
            s += __shfl_xor_sync(0xffffffffu, s, 2);
            s += __shfl_xor_sync(0xffffffffu, s, 1);
            int gj = jlo + j;
            float p = (gj >= wlo && gj <= whi) ? __expf(s) : 0.0f;
            lsum += p;
            float4 vv = *(const float4*)(vs + j*64 + dl*4);
            acc.x += p*vv.x; acc.y += p*vv.y; acc.z += p*vv.z; acc.w += p*vv.w;
        }
        float inv = 1.0f / lsum;
        float* op = g_ctx + (size_t)(b*LL + q) * CC + h*HD + dl*4;
        float4 o;
        o.x = to_tf32(acc.x * inv); o.y = to_tf32(acc.y * inv);
        o.z = to_tf32(acc.z * inv); o.w = to_tf32(acc.w * inv);
        *(float4*)op = o;
    }
}

// ---------------- gated residual combine: smem-transposed, coalesced --------
__global__ void __launch_bounds__(256)
combine_kernel(float* __restrict__ out)
{
    __shared__ float s[32][33];
    int bi = blockIdx.x;
    int ct = bi & 15, lt = (bi >> 4) & 31, b = bi >> 9;
    int c0 = ct * 32, l0 = lt * 32;
    int tx = threadIdx.x & 31, ty = threadIdx.x >> 5;
#pragma unroll
    for (int r = ty; r < 32; r += 8)
        s[r][tx] = g_attnout[(size_t)(b*LL + l0 + r) * CC + c0 + tx];
    __syncthreads();
    float mk = g_mask[b*LL + l0 + tx];
#pragma unroll
    for (int cr = ty; cr < 32; cr += 8) {
        size_t o = (size_t)(b*CC + c0 + cr) * LL + l0 + tx;
        out[o] = g_xwalze[o] + mk * s[tx][cr];
    }
}

// ---------------- host launcher ---------------------------------------------
extern "C" void kernel_launch(void* const* d_in, const int* in_sizes, int n_in,
                              void* d_out, int out_size)
{
    const float* x      = (const float*)d_in[0];
    const float* dw_w   = (const float*)d_in[1];
    const float* dw_b   = (const float*)d_in[2];
    const float* sh_w   = (const float*)d_in[3];
    const float* sh_b   = (const float*)d_in[4];
    const float* mixw   = (const float*)d_in[5];
    const float* gamma  = (const float*)d_in[6];
    const float* beta   = (const float*)d_in[7];
    const float* det_w1 = (const float*)d_in[8];
    const float* det_b1 = (const float*)d_in[9];
    const float* det_w2 = (const float*)d_in[10];
    const float* det_b2 = (const float*)d_in[11];
    const float* ipw    = (const float*)d_in[12];
    const float* ipb    = (const float*)d_in[13];
    const float* opw    = (const float*)d_in[14];
    const float* opb    = (const float*)d_in[15];
    float* out = (float*)d_out;

    float *p_comb, *p_H, *p_qkv, *p_ctx, *p_attnout, *p_ipw, *p_opw, *p_w1;
    cudaGetSymbolAddress((void**)&p_comb,    g_comb);
    cudaGetSymbolAddress((void**)&p_H,       g_H);
    cudaGetSymbolAddress((void**)&p_qkv,     g_qkv);
    cudaGetSymbolAddress((void**)&p_ctx,     g_ctx);
    cudaGetSymbolAddress((void**)&p_attnout, g_attnout);
    cudaGetSymbolAddress((void**)&p_ipw,     g_ipw);
    cudaGetSymbolAddress((void**)&p_opw,     g_opw);
    cudaGetSymbolAddress((void**)&p_w1,      g_w1);

    cudaFuncSetAttribute(mma_gemm<0>, cudaFuncAttributeMaxDynamicSharedMemorySize,
                         GEMM_SMEM);
    cudaFuncSetAttribute(mma_gemm<1>, cudaFuncAttributeMaxDynamicSharedMemorySize,
                         GEMM_SMEM);

    const int NTOT = BB*CC*HH*WW;   // 4,194,304
    const int M = BB*LL;            // 8192

    // 0) round weights to tf32 once
    {
        int tot = 3*CC*CC + CC*CC + 128*2*CC;
        round_weights<<<(tot + 255)/256, 256>>>(ipw, opw, det_w1);
    }

    // 1) walze: dwconv + BN + GELU (spatial layout only)
    walze_kernel<<<NTOT/256, 256>>>(x, dw_w, dw_b, sh_w, sh_b, mixw, gamma, beta);

    // 1b) pack: transpose into comb rows (tf32-rounded), fully coalesced
    pack_kernel<<<BB*16*32, 256>>>(x);

    // 2) detector GEMM: H = gelu(comb(8192,1024) @ det_w1^T + b1)
    {
        dim3 g(1, M/128);
        mma_gemm<1><<<g, 256, GEMM_SMEM>>>(p_comb, 2*CC, p_w1, 2*CC,
                                           det_b1, p_H, 128, 2*CC);
    }
    // 3) detector head -> mask
    det_final_kernel<<<(M*32)/256, 256>>>(det_w2, det_b2);

    // 4) QKV GEMM: qkv = x_after(8192,512) @ in_proj_w^T(512,1536) + b
    {
        dim3 g((3*CC)/128, M/128);
        mma_gemm<0><<<g, 256, GEMM_SMEM>>>(p_comb + CC, 2*CC, p_ipw, CC,
                                           ipb, p_qkv, 3*CC, CC);
    }

    // 5) banded attention (smem-tiled)
    attn_kernel<<<BB*NHD*(LL/64), 256>>>();

    // 6) out_proj GEMM: N=512, K=512
    {
        dim3 g(CC/128, M/128);
        mma_gemm<0><<<g, 256, GEMM_SMEM>>>(p_ctx, CC, p_opw, CC,
                                           opb, p_attnout, CC, CC);
    }

    // 7) gated residual combine (transposed, coalesced)
    combine_kernel<<<BB*16*32, 256>>>(out);
}

// round 5
// speedup vs baseline: 3.8675x; 1.3338x over previous
#include <cuda_runtime.h>
#include <cuda_bf16.h>
#include <math.h>
#include <stdint.h>

#define BB 8
#define CC 512
#define HH 32
#define WW 32
#define LL 1024   // H*W
#define NHD 8
#define HD 64
#define WHALF 16  // WINDOW/2

// ---------------- scratch (static device globals; no runtime allocation) ----
__device__ float g_xwalze[BB*CC*HH*WW];          // (B,C,H,W) post-walze
__device__ __nv_bfloat16 g_comb[BB*LL*2*CC];     // (B*L, 2C): [before | after]
__device__ float g_H[BB*LL*128];                 // detector hidden
__device__ float g_mask[BB*LL];                  // soft mask
__device__ float g_qkv[BB*LL*3*CC];              // (B*L, 3C)
__device__ __nv_bfloat16 g_ctx[BB*LL*CC];        // attention context (bf16)
__device__ float g_attnout[BB*LL*CC];            // out_proj result (B*L, C)
__device__ __nv_bfloat16 g_ipw[3*CC*CC];         // bf16 in_proj_w
__device__ __nv_bfloat16 g_opw[CC*CC];           // bf16 out_proj_w
__device__ __nv_bfloat16 g_w1[128*2*CC];         // bf16 det_w1

__device__ __forceinline__ float gelu_exact(float v) {
    return 0.5f * v * (1.0f + erff(v * 0.70710678118654752440f));
}
__device__ __forceinline__ uint32_t smem_u32(const void* p) {
    uint32_t a;
    asm("{ .reg .u64 t; cvta.to.shared.u64 t, %1; cvt.u32.u64 %0, t; }"
        : "=r"(a) : "l"(p));
    return a;
}
__device__ __forceinline__ void cp16(uint32_t dst, const void* src) {
    asm volatile("cp.async.cg.shared.global [%0], [%1], 16;" :: "r"(dst), "l"(src));
}
__device__ __forceinline__ void ldmx4(uint32_t addr, uint32_t& r0, uint32_t& r1,
                                      uint32_t& r2, uint32_t& r3) {
    asm volatile("ldmatrix.sync.aligned.m8n8.x4.shared.b16 {%0,%1,%2,%3}, [%4];"
                 : "=r"(r0), "=r"(r1), "=r"(r2), "=r"(r3) : "r"(addr));
}
__device__ __forceinline__ void mma16(float* c, uint32_t a0, uint32_t a1,
                                      uint32_t a2, uint32_t a3,
                                      uint32_t b0, uint32_t b1) {
    asm volatile("mma.sync.aligned.m16n8k16.row.col.f32.bf16.bf16.f32 "
                 "{%0,%1,%2,%3}, {%4,%5,%6,%7}, {%8,%9}, {%0,%1,%2,%3};"
                 : "+f"(c[0]), "+f"(c[1]), "+f"(c[2]), "+f"(c[3])
                 : "r"(a0), "r"(a1), "r"(a2), "r"(a3), "r"(b0), "r"(b1));
}

// ====== bf16 mma.sync GEMM: C(M,N) = A(M,K) * B(N,K)^T + bias ===============
// CTA tile (MT*32) x 128, 8 warps (2 m x 4 n). K-chunk 64 bf16 (128B rows),
// double-buffered cp.async, xor-swizzled smem (identical layout to validated
// tf32 version; element width halved, K per mma doubled).
// MT = m-tiles (16 rows) per warp: 4 -> TM=128, 2 -> TM=64.

template<int ACT, int MT>
__global__ void __launch_bounds__(256, 2)
mma_gemm(const __nv_bfloat16* __restrict__ A, int lda,
         const __nv_bfloat16* __restrict__ Bm, int ldb,
         const float* __restrict__ bias,
         float* __restrict__ Cm, int ldc, int K)
{
    constexpr int TM = MT * 32;
    constexpr int ABYTES = TM * 128;          // A tile bytes per buffer
    constexpr int BUFB = ABYTES + 16384;      // bytes per (A+B) buffer
    extern __shared__ char smem[];
    const uint32_t sb = smem_u32(smem);
    const int tid = threadIdx.x, lane = tid & 31, wid = tid >> 5;
    const int bm = blockIdx.y * TM, bn = blockIdx.x * 128;
    const int wm0 = (wid & 1) * (TM / 2), wn0 = (wid >> 1) * 32;

    // cp.async mapping: 8 threads per 128B row (64 bf16), 32 rows per pass
    const int ld_row = tid >> 3;
    const uint32_t st_off =
        (uint32_t)(ld_row * 128 + (((tid & 7) * 16) ^ ((ld_row & 7) << 4)));
    const __nv_bfloat16* Agb = A  + (size_t)(bm + ld_row) * lda + (tid & 7) * 8;
    const __nv_bfloat16* Bgb = Bm + (size_t)(bn + ld_row) * ldb + (tid & 7) * 8;

    auto load_tile = [&](int buf, int ch) {
        uint32_t da = sb + buf * BUFB + st_off;
        uint32_t db = da + ABYTES;
        const __nv_bfloat16* sa  = Agb + ch * 64;
        const __nv_bfloat16* sbp = Bgb + ch * 64;
#pragma unroll
        for (int p = 0; p < MT; p++)
            cp16(da + p * 4096, sa + (size_t)p * 32 * lda);
#pragma unroll
        for (int p = 0; p < 4; p++)
            cp16(db + p * 4096, sbp + (size_t)p * 32 * ldb);
        asm volatile("cp.async.commit_group;" ::: "memory");
    };

    // fragment lane addressing (same as validated tf32 layout)
    const int arow  = wm0 + (lane & 15);
    const uint32_t akb = ((uint32_t)(lane >> 4)) << 4;
    const uint32_t aswz = (uint32_t)((arow & 7) << 4);
    const uint32_t a_rowbase = (uint32_t)(arow * 128);
    const int brow  = wn0 + ((lane >> 4) << 3) + (lane & 7);
    const uint32_t bkb = (uint32_t)(((lane >> 3) & 1) << 4);
    const uint32_t bswz = (uint32_t)((brow & 7) << 4);
    const uint32_t b_rowbase = (uint32_t)(ABYTES + brow * 128);

    float c[MT][4][4];
#pragma unroll
    for (int i = 0; i < MT; i++)
#pragma unroll
        for (int j = 0; j < 4; j++)
#pragma unroll
            for (int k = 0; k < 4; k++) c[i][j][k] = 0.0f;

    const int nch = K >> 6;
    load_tile(0, 0);
    load_tile(1, 1);

    for (int ch = 0; ch < nch; ch++) {
        const int buf = ch & 1;
        if (ch + 1 < nch) asm volatile("cp.async.wait_group 1;" ::: "memory");
        else              asm volatile("cp.async.wait_group 0;" ::: "memory");
        __syncthreads();

        const uint32_t base = sb + buf * BUFB;
#pragma unroll
        for (int ks = 0; ks < 4; ks++) {          // 4 x k16 = 64
            const uint32_t kso = (uint32_t)(ks * 32);
            uint32_t a[MT][4];
#pragma unroll
            for (int mt = 0; mt < MT; mt++)
                ldmx4(base + a_rowbase + (uint32_t)(mt * 2048) + ((kso + akb) ^ aswz),
                      a[mt][0], a[mt][1], a[mt][2], a[mt][3]);
            uint32_t b[4][2];
#pragma unroll
            for (int nt2 = 0; nt2 < 2; nt2++)
                ldmx4(base + b_rowbase + (uint32_t)(nt2 * 2048) + ((kso + bkb) ^ bswz),
                      b[nt2*2][0], b[nt2*2][1], b[nt2*2+1][0], b[nt2*2+1][1]);
#pragma unroll
            for (int mt = 0; mt < MT; mt++)
#pragma unroll
                for (int nt = 0; nt < 4; nt++)
                    mma16(c[mt][nt], a[mt][0], a[mt][1], a[mt][2], a[mt][3],
                          b[nt][0], b[nt][1]);
        }
        __syncthreads();
        if (ch + 2 < nch) load_tile(buf, ch + 2);
    }

#pragma unroll
    for (int mt = 0; mt < MT; mt++) {
        const int r0 = bm + wm0 + mt * 16 + (lane >> 2);
#pragma unroll
        for (int nt = 0; nt < 4; nt++) {
            const int col = bn + wn0 + nt * 8 + (lane & 3) * 2;
            float2 bs = *(const float2*)(bias + col);
            float v0 = c[mt][nt][0] + bs.x, v1 = c[mt][nt][1] + bs.y;
            float v2 = c[mt][nt][2] + bs.x, v3 = c[mt][nt][3] + bs.y;
            if (ACT) {
                v0 = gelu_exact(v0); v1 = gelu_exact(v1);
                v2 = gelu_exact(v2); v3 = gelu_exact(v3);
            }
            *(float2*)(Cm + (size_t)r0 * ldc + col)       = make_float2(v0, v1);
            *(float2*)(Cm + (size_t)(r0 + 8) * ldc + col) = make_float2(v2, v3);
        }
    }
}

// ---------------- weight rounding to bf16 (once per launch) -----------------
__global__ void round_weights(const float* __restrict__ ipw,
                              const float* __restrict__ opw,
                              const float* __restrict__ w1)
{
    int i = blockIdx.x * blockDim.x + threadIdx.x;
    const int N1 = 3*CC*CC, N2 = CC*CC, N3 = 128*2*CC;
    if (i < N1)            g_ipw[i] = __float2bfloat16_rn(ipw[i]);
    else if (i < N1 + N2)  g_opw[i - N1] = __float2bfloat16_rn(opw[i - N1]);
    else if (i < N1 + N2 + N3) g_w1[i - N1 - N2] = __float2bfloat16_rn(w1[i - N1 - N2]);
}

// ---------------- kernel 1: dual depthwise conv + residual + BN + GELU ------
__global__ void walze_kernel(const float* __restrict__ x,
                             const float* __restrict__ dw_w,
                             const float* __restrict__ dw_b,
                             const float* __restrict__ sh_w,
                             const float* __restrict__ sh_b,
                             const float* __restrict__ mixw,
                             const float* __restrict__ gamma,
                             const float* __restrict__ beta)
{
    int idx = blockIdx.x * blockDim.x + threadIdx.x;
    if (idx >= BB*CC*HH*WW) return;
    int w = idx & 31;
    int h = (idx >> 5) & 31;
    int c = (idx >> 10) & 511;
    int b = idx >> 19;

    const float* xb = x + ((size_t)(b*CC + c)) * (HH*WW);
    int hm = (h + HH - 1) & 31, hp = (h + 1) & 31;
    int wm = (w + WW - 1) & 31, wp = (w + 1) & 31;

    float v00 = xb[hm*WW+wm], v01 = xb[hm*WW+w], v02 = xb[hm*WW+wp];
    float v10 = xb[h *WW+wm], v11 = xb[h *WW+w], v12 = xb[h *WW+wp];
    float v20 = xb[hp*WW+wm], v21 = xb[hp*WW+w], v22 = xb[hp*WW+wp];

    const float* dk = dw_w + c*9;
    float main_out = v00*dk[0] + v01*dk[1] + v02*dk[2]
                   + v10*dk[3] + v11*dk[4] + v12*dk[5]
                   + v20*dk[6] + v21*dk[7] + v22*dk[8] + dw_b[c];
    float ex = v00*sh_w[0] + v01*sh_w[1] + v02*sh_w[2]
             + v10*sh_w[3] + v11*sh_w[4] + v12*sh_w[5]
             + v20*sh_w[6] + v21*sh_w[7] + v22*sh_w[8] + sh_b[0];

    float mix = 1.0f / (1.0f + __expf(-mixw[0]));
    float combined = mix * main_out + (1.0f - mix) * ex + v11;
    float bn = gamma[c] * combined * rsqrtf(1.0f + 1e-5f) + beta[c];
    g_xwalze[idx] = gelu_exact(bn);
}

// ---------------- pack: transpose x / x_walze into comb rows (bf16) ---------
__global__ void __launch_bounds__(256)
pack_kernel(const float* __restrict__ x)
{
    __shared__ float sx[32][33];
    __shared__ float sw[32][33];
    int bi = blockIdx.x;
    int lt = bi & 31, ct = (bi >> 5) & 15, b = bi >> 9;
    int c0 = ct * 32, l0 = lt * 32;
    int tx = threadIdx.x & 31, ty = threadIdx.x >> 5;
#pragma unroll
    for (int r = ty; r < 32; r += 8) {
        size_t src = (size_t)(b*CC + c0 + r) * LL + l0 + tx;
        sx[r][tx] = x[src];
        sw[r][tx] = g_xwalze[src];
    }
    __syncthreads();
#pragma unroll
    for (int r = ty; r < 32; r += 8) {   // r = local l index
        size_t dst = (size_t)(b*LL + l0 + r) * (2*CC) + c0 + tx;
        g_comb[dst]      = __float2bfloat16_rn(sx[tx][r]);
        g_comb[dst + CC] = __float2bfloat16_rn(sw[tx][r]);
    }
}

// ---------------- detector head: logits -> sigmoid mask ---------------------
__global__ void det_final_kernel(const float* __restrict__ w2,
                                 const float* __restrict__ b2)
{
    int gw = (blockIdx.x * blockDim.x + threadIdx.x) >> 5;
    int lane = threadIdx.x & 31;
    if (gw >= BB*LL) return;
    float4 hv = *(const float4*)(g_H + (size_t)gw * 128 + lane*4);
    float4 wv = *(const float4*)(w2 + lane*4);
    float s = hv.x*wv.x + hv.y*wv.y + hv.z*wv.z + hv.w*wv.w;
#pragma unroll
    for (int o = 16; o; o >>= 1) s += __shfl_xor_sync(0xffffffffu, s, o);
    if (lane == 0)
        g_mask[gw] = 1.0f / (1.0f + __expf(-(s + b2[0])));
}

// ---------------- banded attention: smem-tiled, 2 queries per warp ----------
__global__ void __launch_bounds__(256)
attn_kernel()
{
    __shared__ float ks[96*64];
    __shared__ float vs[96*64];
    int bi = blockIdx.x;                   // 0..1023
    int qt = bi & 15;
    int h  = (bi >> 4) & 7;
    int b  = bi >> 7;
    int q0 = qt * 64;
    int jlo = max(0, q0 - WHALF);
    int jhi = min(LL - 1, q0 + 63 + WHALF);
    int nrows = jhi - jlo + 1;             // <= 96
    int tid = threadIdx.x;

    const float* kbase = g_qkv + (size_t)(b*LL + jlo) * (3*CC) + CC + h*HD;
    for (int i = tid; i < nrows * 16; i += 256) {
        int r = i >> 4, c = (i & 15) * 4;
        const float* kp = kbase + (size_t)r * (3*CC) + c;
        *(float4*)(ks + r*64 + c) = *(const float4*)kp;
        *(float4*)(vs + r*64 + c) = *(const float4*)(kp + CC);
    }
    __syncthreads();

    int wid = tid >> 5, lane = tid & 31;
    int half = lane >> 4;                  // which query of the pair
    int dl = lane & 15;                    // dims 4*dl .. 4*dl+3

#pragma unroll
    for (int pass = 0; pass < 4; pass++) {
        int qe = q0 + wid*8 + pass*2;      // even query of the pair
        int q  = qe + half;
        const float* qp = g_qkv + (size_t)(b*LL + q) * (3*CC) + h*HD + dl*4;
        float4 qv = *(const float4*)qp;
        qv.x *= 0.125f; qv.y *= 0.125f; qv.z *= 0.125f; qv.w *= 0.125f;

        int wlo = max(0, q - WHALF), whi = min(LL - 1, q + WHALF);
        int plo = max(0, qe - WHALF) - jlo;
        int phi = min(LL - 1, qe + 1 + WHALF) - jlo;

        float lsum = 0.0f;
        float4 acc = make_float4(0.f, 0.f, 0.f, 0.f);
        for (int j = plo; j <= phi; j++) {
            float4 kv = *(const float4*)(ks + j*64 + dl*4);
            float s = qv.x*kv.x + qv.y*kv.y + qv.z*kv.z + qv.w*kv.w;
            s += __shfl_xor_sync(0xffffffffu, s, 8);
            s += __shfl_xor_sync(0xffffffffu, s, 4);
            s += __shfl_xor_sync(0xffffffffu, s, 2);
            s += __shfl_xor_sync(0xffffffffu, s, 1);
            int gj = jlo + j;
            float p = (gj >= wlo && gj <= whi) ? __expf(s) : 0.0f;
            lsum += p;
            float4 vv = *(const float4*)(vs + j*64 + dl*4);
            acc.x += p*vv.x; acc.y += p*vv.y; acc.z += p*vv.z; acc.w += p*vv.w;
        }
        float inv = 1.0f / lsum;
        __nv_bfloat16* op = g_ctx + (size_t)(b*LL + q) * CC + h*HD + dl*4;
        __nv_bfloat162 o01, o23;
        o01 = __floats2bfloat162_rn(acc.x * inv, acc.y * inv);
        o23 = __floats2bfloat162_rn(acc.z * inv, acc.w * inv);
        *(uint2*)op = make_uint2(*(uint32_t*)&o01, *(uint32_t*)&o23);
    }
}

// ---------------- gated residual combine: smem-transposed, coalesced --------
__global__ void __launch_bounds__(256)
combine_kernel(float* __restrict__ out)
{
    __shared__ float s[32][33];
    int bi = blockIdx.x;
    int ct = bi & 15, lt = (bi >> 4) & 31, b = bi >> 9;
    int c0 = ct * 32, l0 = lt * 32;
    int tx = threadIdx.x & 31, ty = threadIdx.x >> 5;
#pragma unroll
    for (int r = ty; r < 32; r += 8)
        s[r][tx] = g_attnout[(size_t)(b*LL + l0 + r) * CC + c0 + tx];
    __syncthreads();
    float mk = g_mask[b*LL + l0 + tx];
#pragma unroll
    for (int cr = ty; cr < 32; cr += 8) {
        size_t o = (size_t)(b*CC + c0 + cr) * LL + l0 + tx;
        out[o] = g_xwalze[o] + mk * s[tx][cr];
    }
}

// ---------------- host launcher ---------------------------------------------
extern "C" void kernel_launch(void* const* d_in, const int* in_sizes, int n_in,
                              void* d_out, int out_size)
{
    const float* x      = (const float*)d_in[0];
    const float* dw_w   = (const float*)d_in[1];
    const float* dw_b   = (const float*)d_in[2];
    const float* sh_w   = (const float*)d_in[3];
    const float* sh_b   = (const float*)d_in[4];
    const float* mixw   = (const float*)d_in[5];
    const float* gamma  = (const float*)d_in[6];
    const float* beta   = (const float*)d_in[7];
    const float* det_w1 = (const float*)d_in[8];
    const float* det_b1 = (const float*)d_in[9];
    const float* det_w2 = (const float*)d_in[10];
    const float* det_b2 = (const float*)d_in[11];
    const float* ipw    = (const float*)d_in[12];
    const float* ipb    = (const float*)d_in[13];
    const float* opw    = (const float*)d_in[14];
    const float* opb    = (const float*)d_in[15];
    float* out = (float*)d_out;

    __nv_bfloat16 *p_comb, *p_ctx, *p_ipw, *p_opw, *p_w1;
    float *p_H, *p_qkv, *p_attnout;
    cudaGetSymbolAddress((void**)&p_comb,    g_comb);
    cudaGetSymbolAddress((void**)&p_H,       g_H);
    cudaGetSymbolAddress((void**)&p_qkv,     g_qkv);
    cudaGetSymbolAddress((void**)&p_ctx,     g_ctx);
    cudaGetSymbolAddress((void**)&p_attnout, g_attnout);
    cudaGetSymbolAddress((void**)&p_ipw,     g_ipw);
    cudaGetSymbolAddress((void**)&p_opw,     g_opw);
    cudaGetSymbolAddress((void**)&p_w1,      g_w1);

    const int SMEM128 = 2 * (128*128 + 16384);   // 65536
    const int SMEM64  = 2 * (64*128  + 16384);   // 49152
    cudaFuncSetAttribute((const void*)mma_gemm<0,4>,
                         cudaFuncAttributeMaxDynamicSharedMemorySize, SMEM128);
    cudaFuncSetAttribute((const void*)mma_gemm<1,2>,
                         cudaFuncAttributeMaxDynamicSharedMemorySize, SMEM64);

    const int NTOT = BB*CC*HH*WW;   // 4,194,304
    const int M = BB*LL;            // 8192

    // 0) round weights to bf16 once
    {
        int tot = 3*CC*CC + CC*CC + 128*2*CC;
        round_weights<<<(tot + 255)/256, 256>>>(ipw, opw, det_w1);
    }

    // 1) walze: dwconv + BN + GELU (spatial layout only)
    walze_kernel<<<NTOT/256, 256>>>(x, dw_w, dw_b, sh_w, sh_b, mixw, gamma, beta);

    // 1b) pack: transpose into comb rows (bf16), fully coalesced
    pack_kernel<<<BB*16*32, 256>>>(x);

    // 2) detector GEMM: H = gelu(comb(8192,1024) @ det_w1^T + b1); 64-row tiles
    {
        dim3 g(1, M/64);
        mma_gemm<1,2><<<g, 256, SMEM64>>>(p_comb, 2*CC, p_w1, 2*CC,
                                          det_b1, p_H, 128, 2*CC);
    }
    // 3) detector head -> mask
    det_final_kernel<<<(M*32)/256, 256>>>(det_w2, det_b2);

    // 4) QKV GEMM: qkv = x_after(8192,512) @ in_proj_w^T(512,1536) + b
    {
        dim3 g((3*CC)/128, M/128);
        mma_gemm<0,4><<<g, 256, SMEM128>>>(p_comb + CC, 2*CC, p_ipw, CC,
                                           ipb, p_qkv, 3*CC, CC);
    }

    // 5) banded attention (smem-tiled)
    attn_kernel<<<BB*NHD*(LL/64), 256>>>();

    // 6) out_proj GEMM: N=512, K=512
    {
        dim3 g(CC/128, M/128);
        mma_gemm<0,4><<<g, 256, SMEM128>>>(p_ctx, CC, p_opw, CC,
                                           opb, p_attnout, CC, CC);
    }

    // 7) gated residual combine (transposed, coalesced)
    combine_kernel<<<BB*16*32, 256>>>(out);
}